// round 1
// baseline (speedup 1.0000x reference)
#include <cuda_runtime.h>
#include <math.h>

// Problem constants
#define Bsz  16
#define Ssz  2048
#define Esz  512
#define Hsz  512
#define HIsz 1024
#define Lsz  3
#define Msz  (Bsz * Ssz)   // 32768 rows

// ---------------------------------------------------------------------------
// Scratch (allocation-free: __device__ globals)
// ---------------------------------------------------------------------------
__device__ float g_xf[(size_t)Msz * Hsz];        // 64 MB  forward stream
__device__ float g_xr[(size_t)Msz * Hsz];        // 64 MB  reverse stream
__device__ float g_hg[(size_t)Msz * 2 * HIsz];   // 256 MB gate GEMM output
__device__ float g_h [(size_t)Msz * HIsz];       // 128 MB scan output

// ---------------------------------------------------------------------------
// fp32 SGEMM: C[M,N] = A[arow(m),K] * B[K,N] (+ bias[N])
// BM=128 BN=128 BK=16 TM=8 TN=8, 256 threads.
// rowidx != nullptr -> gather A rows (embedding lookup).
// Requires M%128==0, N%128==0, K%16==0 (true for all calls here).
// ---------------------------------------------------------------------------
__global__ __launch_bounds__(256)
void sgemm_kernel(const float* __restrict__ A, const float* __restrict__ Bm,
                  float* __restrict__ C, const float* __restrict__ bias,
                  const int* __restrict__ rowidx, int M, int N, int K)
{
    const int BM = 128, BN = 128, BK = 16, TM = 8, TN = 8;
    __shared__ float As[BK][BM];
    __shared__ float Bs[BK][BN];

    const int tid  = threadIdx.x;
    const int bm   = blockIdx.y * BM;
    const int bn   = blockIdx.x * BN;
    const int tcol = tid % (BN / TN);   // 0..15
    const int trow = tid / (BN / TN);   // 0..15

    float acc[TM][TN];
#pragma unroll
    for (int i = 0; i < TM; i++)
#pragma unroll
        for (int j = 0; j < TN; j++) acc[i][j] = 0.f;

    // A tile loads: 128x16 floats = 512 float4, 2 per thread
    const int aRow = tid >> 2;          // 0..63
    const int aCol = (tid & 3) * 4;     // 0,4,8,12
    const float* arow0;
    const float* arow1;
    {
        int m0 = bm + aRow;
        int m1 = bm + aRow + 64;
        int r0 = rowidx ? rowidx[m0] : m0;
        int r1 = rowidx ? rowidx[m1] : m1;
        arow0 = A + (size_t)r0 * K;
        arow1 = A + (size_t)r1 * K;
    }
    // B tile loads: 16x128 floats = 512 float4, 2 per thread
    const int bRow = tid >> 5;          // 0..7
    const int bCol = (tid & 31) * 4;    // 0..124

    for (int k0 = 0; k0 < K; k0 += BK) {
        float4 va0 = *(const float4*)(arow0 + k0 + aCol);
        float4 va1 = *(const float4*)(arow1 + k0 + aCol);
        float4 vb0 = *(const float4*)(Bm + (size_t)(k0 + bRow) * N + bn + bCol);
        float4 vb1 = *(const float4*)(Bm + (size_t)(k0 + bRow + 8) * N + bn + bCol);

        As[aCol + 0][aRow] = va0.x;  As[aCol + 1][aRow] = va0.y;
        As[aCol + 2][aRow] = va0.z;  As[aCol + 3][aRow] = va0.w;
        As[aCol + 0][aRow + 64] = va1.x;  As[aCol + 1][aRow + 64] = va1.y;
        As[aCol + 2][aRow + 64] = va1.z;  As[aCol + 3][aRow + 64] = va1.w;
        *(float4*)&Bs[bRow][bCol]     = vb0;
        *(float4*)&Bs[bRow + 8][bCol] = vb1;
        __syncthreads();

#pragma unroll
        for (int kk = 0; kk < BK; kk++) {
            float ra[TM], rb[TN];
            *(float4*)&ra[0] = *(const float4*)&As[kk][trow * TM];
            *(float4*)&ra[4] = *(const float4*)&As[kk][trow * TM + 4];
            *(float4*)&rb[0] = *(const float4*)&Bs[kk][tcol * TN];
            *(float4*)&rb[4] = *(const float4*)&Bs[kk][tcol * TN + 4];
#pragma unroll
            for (int i = 0; i < TM; i++)
#pragma unroll
                for (int j = 0; j < TN; j++)
                    acc[i][j] += ra[i] * rb[j];
        }
        __syncthreads();
    }

#pragma unroll
    for (int i = 0; i < TM; i++) {
        size_t crow = (size_t)(bm + trow * TM + i) * N + bn;
#pragma unroll
        for (int j = 0; j < TN; j += 4) {
            float4 v;
            v.x = acc[i][j + 0]; v.y = acc[i][j + 1];
            v.z = acc[i][j + 2]; v.w = acc[i][j + 3];
            if (bias) {
                int col = bn + tcol * TN + j;
                v.x += bias[col + 0]; v.y += bias[col + 1];
                v.z += bias[col + 2]; v.w += bias[col + 3];
            }
            *(float4*)(C + crow + tcol * TN + j) = v;
        }
    }
}

// ---------------------------------------------------------------------------
// Log-space minGRU scan. One thread per (b, channel) recurrence.
// hg row layout: [hidden(0..HI-1) | gate(HI..2HI-1)], row = b*S+s.
// h[b,s,c] = exp( a_s + logcumsumexp_j<=s (lv_j - a_j) )
// ---------------------------------------------------------------------------
__global__ void scan_kernel(const float* __restrict__ hg, float* __restrict__ h)
{
    int idx = blockIdx.x * blockDim.x + threadIdx.x;  // 0..B*HI-1
    int b = idx / HIsz, c = idx % HIsz;
    const float* base = hg + (size_t)b * Ssz * 2 * HIsz + c;
    float* ho = h + (size_t)b * Ssz * HIsz + c;

    float a = 0.f, m = -1e30f, r = 0.f;
    for (int s = 0; s < Ssz; s++) {
        float hid  = base[(size_t)s * 2 * HIsz];
        float gate = base[(size_t)s * 2 * HIsz + HIsz];
        // softplus(g) and softplus(-g) share exp(-|g|)
        float e  = expf(-fabsf(gate));
        float l  = log1pf(e);
        float lc  = -(fmaxf(gate, 0.f) + l);         // log(1-z)
        float lvg = -(fmaxf(-gate, 0.f) + l);        // log z
        // log g(hidden)
        float lg = (hid >= 0.f) ? logf(hid + 0.5f)
                                : (hid - log1pf(expf(hid)));  // -softplus(-hid)
        float lv = lvg + lg;

        a += lc;
        float v = lv - a;
        if (v <= m) {
            r += expf(v - m);
        } else {
            r = r * expf(m - v) + 1.f;
            m = v;
        }
        ho[(size_t)s * HIsz] = r * expf(a + m);      // exp(log_h)
    }
}

// ---------------------------------------------------------------------------
// Reverse-rotate: dst[b,s,:] = src[b, S-1-((s + S - len[b]) % S), :]
// (flip along S then circular left shift by pad = S - len; an involution)
// ---------------------------------------------------------------------------
__global__ void rev_kernel(const float* __restrict__ src, float* __restrict__ dst,
                           const int* __restrict__ lens)
{
    int rIdx = blockIdx.x;
    int b = rIdx / Ssz, s = rIdx % Ssz;
    int len = lens[b];
    int t = s + Ssz - len; if (t >= Ssz) t -= Ssz;
    int sidx = Ssz - 1 - t;
    const float4* p = (const float4*)(src + ((size_t)b * Ssz + sidx) * Hsz);
    float4* q = (float4*)(dst + (size_t)rIdx * Hsz);
    q[threadIdx.x] = p[threadIdx.x];                 // 128 threads * float4 = 512 floats
}

// out[b,s, 0:H]  = xf[b,s,:]
// out[b,s, H:2H] = xr[b, revidx(b,s), :]
__global__ void finalize_kernel(const float* __restrict__ xf, const float* __restrict__ xr,
                                const int* __restrict__ lens, float* __restrict__ out)
{
    int rIdx = blockIdx.x;
    int b = rIdx / Ssz, s = rIdx % Ssz;
    int len = lens[b];
    int t = s + Ssz - len; if (t >= Ssz) t -= Ssz;
    int sidx = Ssz - 1 - t;
    float4* o = (float4*)(out + (size_t)rIdx * 2 * Hsz);
    o[threadIdx.x]       = ((const float4*)(xf + (size_t)rIdx * Hsz))[threadIdx.x];
    o[128 + threadIdx.x] = ((const float4*)(xr + ((size_t)b * Ssz + sidx) * Hsz))[threadIdx.x];
}

// seq_h[b,:] = out[b, len[b]-1, :]
__global__ void seq_kernel(const float* __restrict__ out, const int* __restrict__ lens,
                           float* __restrict__ seq)
{
    int b = blockIdx.x;
    int len = lens[b];
    const float* row = out + ((size_t)b * Ssz + (len - 1)) * 2 * Hsz;
    for (int j = threadIdx.x; j < 2 * Hsz; j += blockDim.x)
        seq[(size_t)b * 2 * Hsz + j] = row[j];
}

// ---------------------------------------------------------------------------
extern "C" void kernel_launch(void* const* d_in, const int* in_sizes, int n_in,
                              void* d_out, int out_size)
{
    const int*   x_source  = (const int*)  d_in[0];
    const int*   x_lengths = (const int*)  d_in[1];
    const float* emb       = (const float*)d_in[2];
    const float* W_er      = (const float*)d_in[3];
    const float* b_er      = (const float*)d_in[4];
    const float* Whg_f     = (const float*)d_in[5];
    const float* Wout_f    = (const float*)d_in[6];
    const float* Whg_r     = (const float*)d_in[7];
    const float* Wout_r    = (const float*)d_in[8];
    float* out = (float*)d_out;

    float *xf, *xr, *hg, *h;
    cudaGetSymbolAddress((void**)&xf, g_xf);
    cudaGetSymbolAddress((void**)&xr, g_xr);
    cudaGetSymbolAddress((void**)&hg, g_hg);
    cudaGetSymbolAddress((void**)&h,  g_h);

    // 1) x_emb = emb[x_source] @ W_er + b_er  -> xf
    sgemm_kernel<<<dim3(Hsz / 128, Msz / 128), 256>>>(
        emb, W_er, xf, b_er, x_source, Msz, Hsz, Esz);

    // 2) reversed stream
    rev_kernel<<<Msz, 128>>>(xf, xr, x_lengths);

    // 3) layers
    for (int l = 0; l < Lsz; l++) {
        // forward direction
        sgemm_kernel<<<dim3(2 * HIsz / 128, Msz / 128), 256>>>(
            xf, Whg_f + (size_t)l * Hsz * 2 * HIsz, hg, nullptr, nullptr,
            Msz, 2 * HIsz, Hsz);
        scan_kernel<<<(Bsz * HIsz) / 128, 128>>>(hg, h);
        sgemm_kernel<<<dim3(Hsz / 128, Msz / 128), 256>>>(
            h, Wout_f + (size_t)l * HIsz * Hsz, xf, nullptr, nullptr,
            Msz, Hsz, HIsz);
        // reverse direction
        sgemm_kernel<<<dim3(2 * HIsz / 128, Msz / 128), 256>>>(
            xr, Whg_r + (size_t)l * Hsz * 2 * HIsz, hg, nullptr, nullptr,
            Msz, 2 * HIsz, Hsz);
        scan_kernel<<<(Bsz * HIsz) / 128, 128>>>(hg, h);
        sgemm_kernel<<<dim3(Hsz / 128, Msz / 128), 256>>>(
            h, Wout_r + (size_t)l * HIsz * Hsz, xr, nullptr, nullptr,
            Msz, Hsz, HIsz);
    }

    // 4) concat(+un-reverse) and last-token gather
    finalize_kernel<<<Msz, 128>>>(xf, xr, x_lengths, out);
    long long need = (long long)Msz * 2 * Hsz + (long long)Bsz * 2 * Hsz;
    if ((long long)out_size >= need)
        seq_kernel<<<Bsz, 256>>>(out, x_lengths, out + (size_t)Msz * 2 * Hsz);
}

// round 3
// speedup vs baseline: 1.4997x; 1.4997x over previous
#include <cuda_runtime.h>
#include <cuda_bf16.h>
#include <math.h>
#include <stdint.h>

// Problem constants
#define Bsz  16
#define Ssz  2048
#define Esz  512
#define Hsz  512
#define HIsz 1024
#define Lsz  3
#define Msz  (Bsz * Ssz)   // 32768 rows
#define Vsz  32000

// ---------------------------------------------------------------------------
// Scratch (allocation-free: __device__ globals)
// ---------------------------------------------------------------------------
__device__ float g_xf[(size_t)Msz * Hsz];
__device__ float g_xr[(size_t)Msz * Hsz];
__device__ float g_hg[(size_t)Msz * 2 * HIsz];
__device__ float g_h [(size_t)Msz * HIsz];
__device__ __nv_bfloat16 g_ah[(size_t)Msz * HIsz];
__device__ __nv_bfloat16 g_al[(size_t)Msz * HIsz];
__device__ __nv_bfloat16 g_embh[(size_t)Vsz * Esz];
__device__ __nv_bfloat16 g_embl[(size_t)Vsz * Esz];
#define NWELEM 9699328
__device__ __nv_bfloat16 g_wh[NWELEM];
__device__ __nv_bfloat16 g_wl[NWELEM];

#define OFF_ER    0
#define OFF_HGF   262144
#define OFF_OUTF  3407872
#define OFF_HGR   4980736
#define OFF_OUTR  8126464

// ---------------------------------------------------------------------------
// PTX helpers (baseline ISA only: cp.async / ldmatrix / mma.sync)
// ---------------------------------------------------------------------------
__device__ __forceinline__ uint32_t s2u(const void* p) {
    uint32_t a;
    asm("{ .reg .u64 t; cvta.to.shared.u64 t, %1; cvt.u32.u64 %0, t; }" : "=r"(a) : "l"(p));
    return a;
}
__device__ __forceinline__ void cp16(uint32_t d, const void* s) {
    asm volatile("cp.async.cg.shared.global [%0], [%1], 16;" :: "r"(d), "l"(s));
}
__device__ __forceinline__ void cp_commit() { asm volatile("cp.async.commit_group;"); }
__device__ __forceinline__ void cp_wait1()  { asm volatile("cp.async.wait_group 1;"); }
__device__ __forceinline__ void ldm_x4(uint32_t addr, uint32_t& r0, uint32_t& r1,
                                       uint32_t& r2, uint32_t& r3) {
    asm volatile("ldmatrix.sync.aligned.m8n8.x4.shared.b16 {%0,%1,%2,%3}, [%4];"
                 : "=r"(r0), "=r"(r1), "=r"(r2), "=r"(r3) : "r"(addr));
}
__device__ __forceinline__ void mma_bf16(float& c0, float& c1, float& c2, float& c3,
                                         uint32_t a0, uint32_t a1, uint32_t a2, uint32_t a3,
                                         uint32_t b0, uint32_t b1) {
    asm volatile("mma.sync.aligned.m16n8k16.row.col.f32.bf16.bf16.f32 "
                 "{%0,%1,%2,%3}, {%4,%5,%6,%7}, {%8,%9}, {%0,%1,%2,%3};"
                 : "+f"(c0), "+f"(c1), "+f"(c2), "+f"(c3)
                 : "r"(a0), "r"(a1), "r"(a2), "r"(a3), "r"(b0), "r"(b1));
}

// ---------------------------------------------------------------------------
// bf16-split GEMM via mma.sync: C[M,N] = A[M,K] * B^T  (B stored [N,K])
// acc(fp32) += Ah*Bh + Ah*Bl + Al*Bh.  Tile 128x128, BK=32, 8 warps (2x4).
// Smem tiles padded to 80B rows (conflict-free ldmatrix).
// ---------------------------------------------------------------------------
#define GT 256
#define ROWP 40                      // padded row, elements
#define TILE_B (128 * ROWP * 2)      // 10240 B per operand tile
#define STAGE_B (4 * TILE_B)         // 40960 B per stage
#define GSM (2 * STAGE_B)            // 81920 B

__global__ __launch_bounds__(GT, 1)
void gemm_kernel(const __nv_bfloat16* __restrict__ Ah, const __nv_bfloat16* __restrict__ Al,
                 const __nv_bfloat16* __restrict__ Bh, const __nv_bfloat16* __restrict__ Bl,
                 float* __restrict__ C, const float* __restrict__ bias,
                 const int* __restrict__ rowidx, int N, int K)
{
    extern __shared__ char smem[];
    const uint32_t sbase = s2u(smem);

    const int tid = threadIdx.x;
    const int wid = tid >> 5, lid = tid & 31;
    const int bm = blockIdx.y * 128, bn = blockIdx.x * 128;
    const int wm = (wid & 1) * 64;        // warp m-offset
    const int wn = (wid >> 1) * 32;       // warp n-offset

    // ---- cp.async source/dest slots: 8 x 16B chunks per thread ----
    const __nv_bfloat16* gsrc[8];
    uint32_t soff[8];
#pragma unroll
    for (int j = 0; j < 8; j++) {
        int cidx = tid + j * GT;          // 0..2047
        int tile = cidx >> 9;             // 0:Ah 1:Al 2:Bh 3:Bl
        int idx  = cidx & 511;
        int row  = idx >> 2;
        int seg  = idx & 3;               // 16B segment within 64B of row data
        soff[j] = (uint32_t)(tile * TILE_B + row * (ROWP * 2) + seg * 16);
        if (tile < 2) {
            long ra = rowidx ? (long)rowidx[bm + row] : (long)(bm + row);
            gsrc[j] = (tile == 0 ? Ah : Al) + ra * (long)K + seg * 8;
        } else {
            long rb = bn + row;
            gsrc[j] = (tile == 2 ? Bh : Bl) + rb * (long)K + seg * 8;
        }
    }

    // ---- ldmatrix smem offsets (within stage, bytes) ----
    // A 16x16 tile at (wm + mt*16, k16*16): lanes0-7 rows0-7 k0 | 8-15 rows8-15 k0
    //                                       | 16-23 rows0-7 k+8 | 24-31 rows8-15 k+8
    uint32_t aoff[4];                      // per m-tile, k16=0, hi-tile base
#pragma unroll
    for (int mt = 0; mt < 4; mt++) {
        int r = wm + mt * 16 + (lid & 15);
        int c = (lid >> 4) * 8;
        aoff[mt] = (uint32_t)(r * (ROWP * 2) + c * 2);
    }
    // B 16x16 (two n8 tiles): lanes0-7 n0-7 k0 | 8-15 n0-7 k+8 | 16-23 n8-15 k0 | 24-31 n8-15 k+8
    uint32_t boff[2];                      // per n16-pair
#pragma unroll
    for (int np = 0; np < 2; np++) {
        int r = wn + np * 16 + (lid & 7) + ((lid >> 4) << 3);
        int c = ((lid >> 3) & 1) * 8;
        boff[np] = (uint32_t)(r * (ROWP * 2) + c * 2);
    }

    float acc[4][4][4];
#pragma unroll
    for (int i = 0; i < 4; i++)
#pragma unroll
        for (int j = 0; j < 4; j++)
#pragma unroll
            for (int q = 0; q < 4; q++) acc[i][j][q] = 0.f;

    const int nst = K >> 5;   // BK=32 stages

    auto load_stage = [&](int s) {
        uint32_t base = sbase + (uint32_t)(s & 1) * STAGE_B;
        int ko = s << 5;
#pragma unroll
        for (int j = 0; j < 8; j++) cp16(base + soff[j], gsrc[j] + ko);
    };

    load_stage(0); cp_commit();
    load_stage(1); cp_commit();

    for (int s = 0; s < nst; s++) {
        cp_wait1();
        __syncthreads();
        uint32_t base = sbase + (uint32_t)(s & 1) * STAGE_B;

#pragma unroll
        for (int k16 = 0; k16 < 2; k16++) {
            uint32_t koff = (uint32_t)(k16 * 32);          // 16 elements * 2B
            uint32_t ah[4][4], al[4][4];
#pragma unroll
            for (int mt = 0; mt < 4; mt++) {
                ldm_x4(base + aoff[mt] + koff,
                       ah[mt][0], ah[mt][1], ah[mt][2], ah[mt][3]);
                ldm_x4(base + TILE_B + aoff[mt] + koff,
                       al[mt][0], al[mt][1], al[mt][2], al[mt][3]);
            }
            uint32_t bh[4][2], bl[4][2];
#pragma unroll
            for (int np = 0; np < 2; np++) {
                uint32_t r0, r1, r2, r3;
                ldm_x4(base + 2 * TILE_B + boff[np] + koff, r0, r1, r2, r3);
                bh[np * 2][0] = r0; bh[np * 2][1] = r1;
                bh[np * 2 + 1][0] = r2; bh[np * 2 + 1][1] = r3;
                ldm_x4(base + 3 * TILE_B + boff[np] + koff, r0, r1, r2, r3);
                bl[np * 2][0] = r0; bl[np * 2][1] = r1;
                bl[np * 2 + 1][0] = r2; bl[np * 2 + 1][1] = r3;
            }
#pragma unroll
            for (int mt = 0; mt < 4; mt++)
#pragma unroll
                for (int nt = 0; nt < 4; nt++) {
                    float* c = acc[mt][nt];
                    mma_bf16(c[0], c[1], c[2], c[3],
                             ah[mt][0], ah[mt][1], ah[mt][2], ah[mt][3],
                             bh[nt][0], bh[nt][1]);
                    mma_bf16(c[0], c[1], c[2], c[3],
                             ah[mt][0], ah[mt][1], ah[mt][2], ah[mt][3],
                             bl[nt][0], bl[nt][1]);
                    mma_bf16(c[0], c[1], c[2], c[3],
                             al[mt][0], al[mt][1], al[mt][2], al[mt][3],
                             bh[nt][0], bh[nt][1]);
                }
        }
        __syncthreads();
        if (s + 2 < nst) load_stage(s + 2);
        cp_commit();
    }

    // ---- epilogue ----
#pragma unroll
    for (int mt = 0; mt < 4; mt++) {
        int r0 = bm + wm + mt * 16 + (lid >> 2);
#pragma unroll
        for (int nt = 0; nt < 4; nt++) {
            int col = bn + wn + nt * 8 + (lid & 3) * 2;
            float2 v0 = make_float2(acc[mt][nt][0], acc[mt][nt][1]);
            float2 v1 = make_float2(acc[mt][nt][2], acc[mt][nt][3]);
            if (bias) {
                float2 bb = *(const float2*)(bias + col);
                v0.x += bb.x; v0.y += bb.y; v1.x += bb.x; v1.y += bb.y;
            }
            *(float2*)(C + (size_t)r0 * N + col) = v0;
            *(float2*)(C + (size_t)(r0 + 8) * N + col) = v1;
        }
    }
}

// ---------------------------------------------------------------------------
// fp32 -> bf16 hi/lo split
// ---------------------------------------------------------------------------
__global__ void split_kernel(const float* __restrict__ x, __nv_bfloat16* __restrict__ h,
                             __nv_bfloat16* __restrict__ l, size_t n)
{
    size_t i = ((size_t)blockIdx.x * blockDim.x + threadIdx.x) * 8;
    if (i >= n) return;
    float4 a = *(const float4*)(x + i);
    float4 b = *(const float4*)(x + i + 4);
    float v[8] = {a.x, a.y, a.z, a.w, b.x, b.y, b.z, b.w};
    struct alignas(16) B8 { __nv_bfloat16 d[8]; } hh, ll;
#pragma unroll
    for (int j = 0; j < 8; j++) {
        hh.d[j] = __float2bfloat16(v[j]);
        ll.d[j] = __float2bfloat16(v[j] - __bfloat162float(hh.d[j]));
    }
    *(B8*)(h + i) = hh;
    *(B8*)(l + i) = ll;
}

// ---------------------------------------------------------------------------
// weight transpose + split: W fp32 [K,N] -> Th/Tl bf16 [N,K]
// ---------------------------------------------------------------------------
__global__ void wsplit_kernel(const float* __restrict__ W, __nv_bfloat16* __restrict__ Th,
                              __nv_bfloat16* __restrict__ Tl, int K, int N)
{
    __shared__ float t[32][33];
    int n0 = blockIdx.x * 32, k0 = blockIdx.y * 32;
    int tx = threadIdx.x, ty = threadIdx.y;
    for (int r = ty; r < 32; r += 8)
        t[r][tx] = W[(size_t)(k0 + r) * N + n0 + tx];
    __syncthreads();
    for (int r = ty; r < 32; r += 8) {
        float v = t[tx][r];
        __nv_bfloat16 hi = __float2bfloat16(v);
        __nv_bfloat16 lo = __float2bfloat16(v - __bfloat162float(hi));
        size_t o = (size_t)(n0 + r) * K + k0 + tx;
        Th[o] = hi; Tl[o] = lo;
    }
}

// ---------------------------------------------------------------------------
// Log-space minGRU scan
// ---------------------------------------------------------------------------
__global__ void scan_kernel(const float* __restrict__ hg, float* __restrict__ h)
{
    int idx = blockIdx.x * blockDim.x + threadIdx.x;
    int b = idx / HIsz, c = idx % HIsz;
    const float* base = hg + (size_t)b * Ssz * 2 * HIsz + c;
    float* ho = h + (size_t)b * Ssz * HIsz + c;

    float a = 0.f, m = -1e30f, r = 0.f;
    for (int s = 0; s < Ssz; s++) {
        float hid  = base[(size_t)s * 2 * HIsz];
        float gate = base[(size_t)s * 2 * HIsz + HIsz];
        float e  = expf(-fabsf(gate));
        float lg1 = log1pf(e);
        float lc  = -(fmaxf(gate, 0.f) + lg1);
        float lvg = -(fmaxf(-gate, 0.f) + lg1);
        float lg = (hid >= 0.f) ? logf(hid + 0.5f)
                                : (hid - log1pf(expf(hid)));
        float lv = lvg + lg;

        a += lc;
        float v = lv - a;
        if (v <= m) {
            r += expf(v - m);
        } else {
            r = r * expf(m - v) + 1.f;
            m = v;
        }
        ho[(size_t)s * HIsz] = r * expf(a + m);
    }
}

// ---------------------------------------------------------------------------
// reverse-rotate / finalize / last-token gather
// ---------------------------------------------------------------------------
__global__ void rev_kernel(const float* __restrict__ src, float* __restrict__ dst,
                           const int* __restrict__ lens)
{
    int rIdx = blockIdx.x;
    int b = rIdx / Ssz, s = rIdx % Ssz;
    int len = lens[b];
    int t = s + Ssz - len; if (t >= Ssz) t -= Ssz;
    int sidx = Ssz - 1 - t;
    const float4* p = (const float4*)(src + ((size_t)b * Ssz + sidx) * Hsz);
    float4* q = (float4*)(dst + (size_t)rIdx * Hsz);
    q[threadIdx.x] = p[threadIdx.x];
}

__global__ void finalize_kernel(const float* __restrict__ xf, const float* __restrict__ xr,
                                const int* __restrict__ lens, float* __restrict__ out)
{
    int rIdx = blockIdx.x;
    int b = rIdx / Ssz, s = rIdx % Ssz;
    int len = lens[b];
    int t = s + Ssz - len; if (t >= Ssz) t -= Ssz;
    int sidx = Ssz - 1 - t;
    float4* o = (float4*)(out + (size_t)rIdx * 2 * Hsz);
    o[threadIdx.x]       = ((const float4*)(xf + (size_t)rIdx * Hsz))[threadIdx.x];
    o[128 + threadIdx.x] = ((const float4*)(xr + ((size_t)b * Ssz + sidx) * Hsz))[threadIdx.x];
}

__global__ void seq_kernel(const float* __restrict__ out, const int* __restrict__ lens,
                           float* __restrict__ seq)
{
    int b = blockIdx.x;
    int len = lens[b];
    const float* row = out + ((size_t)b * Ssz + (len - 1)) * 2 * Hsz;
    for (int j = threadIdx.x; j < 2 * Hsz; j += blockDim.x)
        seq[(size_t)b * 2 * Hsz + j] = row[j];
}

// ---------------------------------------------------------------------------
extern "C" void kernel_launch(void* const* d_in, const int* in_sizes, int n_in,
                              void* d_out, int out_size)
{
    const int*   x_source  = (const int*)  d_in[0];
    const int*   x_lengths = (const int*)  d_in[1];
    const float* emb       = (const float*)d_in[2];
    const float* W_er      = (const float*)d_in[3];
    const float* b_er      = (const float*)d_in[4];
    const float* Whg_f     = (const float*)d_in[5];
    const float* Wout_f    = (const float*)d_in[6];
    const float* Whg_r     = (const float*)d_in[7];
    const float* Wout_r    = (const float*)d_in[8];
    float* out = (float*)d_out;

    float *xf, *xr, *hg, *h;
    __nv_bfloat16 *ah, *al, *embh, *embl, *wh, *wl;
    cudaGetSymbolAddress((void**)&xf,   g_xf);
    cudaGetSymbolAddress((void**)&xr,   g_xr);
    cudaGetSymbolAddress((void**)&hg,   g_hg);
    cudaGetSymbolAddress((void**)&h,    g_h);
    cudaGetSymbolAddress((void**)&ah,   g_ah);
    cudaGetSymbolAddress((void**)&al,   g_al);
    cudaGetSymbolAddress((void**)&embh, g_embh);
    cudaGetSymbolAddress((void**)&embl, g_embl);
    cudaGetSymbolAddress((void**)&wh,   g_wh);
    cudaGetSymbolAddress((void**)&wl,   g_wl);

    cudaFuncSetAttribute(gemm_kernel, cudaFuncAttributeMaxDynamicSharedMemorySize, GSM);

    // ---- weight transpose + split ----
    wsplit_kernel<<<dim3(Esz / 32, Esz / 32), dim3(32, 8)>>>(W_er, wh + OFF_ER, wl + OFF_ER, Esz, Hsz);
    for (int l = 0; l < Lsz; l++) {
        wsplit_kernel<<<dim3(2 * HIsz / 32, Hsz / 32), dim3(32, 8)>>>(
            Whg_f + (size_t)l * Hsz * 2 * HIsz, wh + OFF_HGF + (size_t)l * 1048576,
            wl + OFF_HGF + (size_t)l * 1048576, Hsz, 2 * HIsz);
        wsplit_kernel<<<dim3(Hsz / 32, HIsz / 32), dim3(32, 8)>>>(
            Wout_f + (size_t)l * HIsz * Hsz, wh + OFF_OUTF + (size_t)l * 524288,
            wl + OFF_OUTF + (size_t)l * 524288, HIsz, Hsz);
        wsplit_kernel<<<dim3(2 * HIsz / 32, Hsz / 32), dim3(32, 8)>>>(
            Whg_r + (size_t)l * Hsz * 2 * HIsz, wh + OFF_HGR + (size_t)l * 1048576,
            wl + OFF_HGR + (size_t)l * 1048576, Hsz, 2 * HIsz);
        wsplit_kernel<<<dim3(Hsz / 32, HIsz / 32), dim3(32, 8)>>>(
            Wout_r + (size_t)l * HIsz * Hsz, wh + OFF_OUTR + (size_t)l * 524288,
            wl + OFF_OUTR + (size_t)l * 524288, HIsz, Hsz);
    }
    split_kernel<<<(unsigned)(((size_t)Vsz * Esz) / 2048), 256>>>(emb, embh, embl, (size_t)Vsz * Esz);

    // ---- embed GEMM ----
    gemm_kernel<<<dim3(Hsz / 128, Msz / 128), GT, GSM>>>(
        embh, embl, wh + OFF_ER, wl + OFF_ER, xf, b_er, x_source, Hsz, Esz);

    rev_kernel<<<Msz, 128>>>(xf, xr, x_lengths);

    for (int l = 0; l < Lsz; l++) {
        split_kernel<<<(unsigned)(((size_t)Msz * Hsz) / 2048), 256>>>(xf, ah, al, (size_t)Msz * Hsz);
        gemm_kernel<<<dim3(2 * HIsz / 128, Msz / 128), GT, GSM>>>(
            ah, al, wh + OFF_HGF + (size_t)l * 1048576, wl + OFF_HGF + (size_t)l * 1048576,
            hg, nullptr, nullptr, 2 * HIsz, Hsz);
        scan_kernel<<<(Bsz * HIsz) / 128, 128>>>(hg, h);
        split_kernel<<<(unsigned)(((size_t)Msz * HIsz) / 2048), 256>>>(h, ah, al, (size_t)Msz * HIsz);
        gemm_kernel<<<dim3(Hsz / 128, Msz / 128), GT, GSM>>>(
            ah, al, wh + OFF_OUTF + (size_t)l * 524288, wl + OFF_OUTF + (size_t)l * 524288,
            xf, nullptr, nullptr, Hsz, HIsz);

        split_kernel<<<(unsigned)(((size_t)Msz * Hsz) / 2048), 256>>>(xr, ah, al, (size_t)Msz * Hsz);
        gemm_kernel<<<dim3(2 * HIsz / 128, Msz / 128), GT, GSM>>>(
            ah, al, wh + OFF_HGR + (size_t)l * 1048576, wl + OFF_HGR + (size_t)l * 1048576,
            hg, nullptr, nullptr, 2 * HIsz, Hsz);
        scan_kernel<<<(Bsz * HIsz) / 128, 128>>>(hg, h);
        split_kernel<<<(unsigned)(((size_t)Msz * HIsz) / 2048), 256>>>(h, ah, al, (size_t)Msz * HIsz);
        gemm_kernel<<<dim3(Hsz / 128, Msz / 128), GT, GSM>>>(
            ah, al, wh + OFF_OUTR + (size_t)l * 524288, wl + OFF_OUTR + (size_t)l * 524288,
            xr, nullptr, nullptr, Hsz, HIsz);
    }

    finalize_kernel<<<Msz, 128>>>(xf, xr, x_lengths, out);
    long long need = (long long)Msz * 2 * Hsz + (long long)Bsz * 2 * Hsz;
    if ((long long)out_size >= need)
        seq_kernel<<<Bsz, 256>>>(out, x_lengths, out + (size_t)Msz * 2 * Hsz);
}

// round 4
// speedup vs baseline: 5.3404x; 3.5609x over previous
#include <cuda_runtime.h>
#include <cuda_fp16.h>
#include <math.h>
#include <stdint.h>

// Problem constants
#define Bsz  16
#define Ssz  2048
#define Esz  512
#define Hsz  512
#define HIsz 1024
#define Lsz  3
#define Msz  (Bsz * Ssz)
#define Vsz  32000

// ---------------------------------------------------------------------------
// Scratch (__device__ globals; allocation-free)
// ---------------------------------------------------------------------------
__device__ float  g_xf[(size_t)Msz * Hsz];           // final fwd fp32
__device__ float  g_xr[(size_t)Msz * Hsz];           // final rev fp32
__device__ __half g_x16f[(size_t)Msz * Hsz];         // fwd activations fp16
__device__ __half g_x16r[(size_t)Msz * Hsz];         // rev activations fp16
__device__ __half g_hg16[(size_t)Msz * 2 * HIsz];    // gate GEMM out fp16
__device__ __half g_h16[(size_t)Msz * HIsz];         // scan out fp16
__device__ __half g_emb16[(size_t)Vsz * Esz];
#define NWELEM 9699328
__device__ __half g_w16[NWELEM];                     // transposed weights fp16

#define OFF_ER    0
#define OFF_HGF   262144
#define OFF_OUTF  3407872
#define OFF_HGR   4980736
#define OFF_OUTR  8126464

// ---------------------------------------------------------------------------
// PTX helpers (baseline sm_103 ISA: cp.async / ldmatrix / mma.sync only)
// ---------------------------------------------------------------------------
__device__ __forceinline__ uint32_t s2u(const void* p) {
    uint32_t a;
    asm("{ .reg .u64 t; cvta.to.shared.u64 t, %1; cvt.u32.u64 %0, t; }" : "=r"(a) : "l"(p));
    return a;
}
__device__ __forceinline__ void cp16(uint32_t d, const void* s) {
    asm volatile("cp.async.cg.shared.global [%0], [%1], 16;" :: "r"(d), "l"(s));
}
__device__ __forceinline__ void cp_commit() { asm volatile("cp.async.commit_group;"); }
__device__ __forceinline__ void cp_wait2()  { asm volatile("cp.async.wait_group 2;"); }
__device__ __forceinline__ void ldm_x4(uint32_t addr, uint32_t& r0, uint32_t& r1,
                                       uint32_t& r2, uint32_t& r3) {
    asm volatile("ldmatrix.sync.aligned.m8n8.x4.shared.b16 {%0,%1,%2,%3}, [%4];"
                 : "=r"(r0), "=r"(r1), "=r"(r2), "=r"(r3) : "r"(addr));
}
__device__ __forceinline__ void mma_fp16(float& c0, float& c1, float& c2, float& c3,
                                         uint32_t a0, uint32_t a1, uint32_t a2, uint32_t a3,
                                         uint32_t b0, uint32_t b1) {
    asm volatile("mma.sync.aligned.m16n8k16.row.col.f32.f16.f16.f32 "
                 "{%0,%1,%2,%3}, {%4,%5,%6,%7}, {%8,%9}, {%0,%1,%2,%3};"
                 : "+f"(c0), "+f"(c1), "+f"(c2), "+f"(c3)
                 : "r"(a0), "r"(a1), "r"(a2), "r"(a3), "r"(b0), "r"(b1));
}

// ---------------------------------------------------------------------------
// fp16 GEMM: C[M,N] = A[M,K] * B^T  (B stored [N,K] row-major)
// Tile 128x128, BK=32, 8 warps (2x4), 4-stage cp.async, 1 barrier/stage.
// Outputs: C32 (fp32, optional) and/or C16 (fp16, optional); bias on both.
// ---------------------------------------------------------------------------
#define GT 256
#define ROWB 80                       // padded row bytes (40 fp16)
#define TILE_B (128 * ROWB)           // 10240 B
#define STAGE_B (2 * TILE_B)          // 20480 B
#define GSM (4 * STAGE_B)             // 81920 B

__global__ __launch_bounds__(GT, 2)
void gemm_kernel(const __half* __restrict__ A, const __half* __restrict__ Bm,
                 float* __restrict__ C32, __half* __restrict__ C16,
                 const float* __restrict__ bias,
                 const int* __restrict__ rowidx, int N, int K)
{
    extern __shared__ char smem[];
    const uint32_t sbase = s2u(smem);

    const int tid = threadIdx.x;
    const int wid = tid >> 5, lid = tid & 31;
    const int bm = blockIdx.y * 128, bn = blockIdx.x * 128;
    const int wm = (wid & 1) * 64;
    const int wn = (wid >> 1) * 32;

    // cp.async slots: 4 x 16B per thread (A 512 chunks + B 512 chunks)
    const __half* gsrc[4];
    uint32_t soff[4];
#pragma unroll
    for (int j = 0; j < 4; j++) {
        int cidx = tid + j * GT;          // 0..1023
        int tile = cidx >> 9;             // 0:A 1:B
        int idx  = cidx & 511;
        int row  = idx >> 2;
        int seg  = idx & 3;
        soff[j] = (uint32_t)(tile * TILE_B + row * ROWB + seg * 16);
        if (tile == 0) {
            long ra = rowidx ? (long)rowidx[bm + row] : (long)(bm + row);
            gsrc[j] = A + ra * (long)K + seg * 8;
        } else {
            gsrc[j] = Bm + (long)(bn + row) * K + seg * 8;
        }
    }

    // ldmatrix offsets
    uint32_t aoff[4];
#pragma unroll
    for (int mt = 0; mt < 4; mt++) {
        int r = wm + mt * 16 + (lid & 15);
        int c = (lid >> 4) * 8;
        aoff[mt] = (uint32_t)(r * ROWB + c * 2);
    }
    uint32_t boff[2];
#pragma unroll
    for (int np = 0; np < 2; np++) {
        int r = wn + np * 16 + (lid & 7) + ((lid >> 4) << 3);
        int c = ((lid >> 3) & 1) * 8;
        boff[np] = (uint32_t)(TILE_B + r * ROWB + c * 2);
    }

    float acc[4][4][4];
#pragma unroll
    for (int i = 0; i < 4; i++)
#pragma unroll
        for (int j = 0; j < 4; j++)
#pragma unroll
            for (int q = 0; q < 4; q++) acc[i][j][q] = 0.f;

    const int nst = K >> 5;

    auto load_stage = [&](int s) {
        uint32_t base = sbase + (uint32_t)(s & 3) * STAGE_B;
        int ko = s << 5;
#pragma unroll
        for (int j = 0; j < 4; j++) cp16(base + soff[j], gsrc[j] + ko);
    };

    load_stage(0); cp_commit();
    load_stage(1); cp_commit();
    load_stage(2); cp_commit();

    for (int s = 0; s < nst; s++) {
        cp_wait2();
        __syncthreads();
        if (s + 3 < nst) load_stage(s + 3);
        cp_commit();

        uint32_t base = sbase + (uint32_t)(s & 3) * STAGE_B;
#pragma unroll
        for (int k16 = 0; k16 < 2; k16++) {
            uint32_t koff = (uint32_t)(k16 * 32);
            uint32_t af[4][4];
#pragma unroll
            for (int mt = 0; mt < 4; mt++)
                ldm_x4(base + aoff[mt] + koff, af[mt][0], af[mt][1], af[mt][2], af[mt][3]);
            uint32_t bf[4][2];
#pragma unroll
            for (int np = 0; np < 2; np++) {
                uint32_t r0, r1, r2, r3;
                ldm_x4(base + boff[np] + koff, r0, r1, r2, r3);
                bf[np * 2][0] = r0;     bf[np * 2][1] = r1;
                bf[np * 2 + 1][0] = r2; bf[np * 2 + 1][1] = r3;
            }
#pragma unroll
            for (int mt = 0; mt < 4; mt++)
#pragma unroll
                for (int nt = 0; nt < 4; nt++)
                    mma_fp16(acc[mt][nt][0], acc[mt][nt][1], acc[mt][nt][2], acc[mt][nt][3],
                             af[mt][0], af[mt][1], af[mt][2], af[mt][3],
                             bf[nt][0], bf[nt][1]);
        }
    }

    // epilogue
#pragma unroll
    for (int mt = 0; mt < 4; mt++) {
        int r0 = bm + wm + mt * 16 + (lid >> 2);
#pragma unroll
        for (int nt = 0; nt < 4; nt++) {
            int col = bn + wn + nt * 8 + (lid & 3) * 2;
            float v0 = acc[mt][nt][0], v1 = acc[mt][nt][1];
            float v2 = acc[mt][nt][2], v3 = acc[mt][nt][3];
            if (bias) {
                float2 bb = *(const float2*)(bias + col);
                v0 += bb.x; v1 += bb.y; v2 += bb.x; v3 += bb.y;
            }
            if (C32) {
                *(float2*)(C32 + (size_t)r0 * N + col) = make_float2(v0, v1);
                *(float2*)(C32 + (size_t)(r0 + 8) * N + col) = make_float2(v2, v3);
            }
            if (C16) {
                *(__half2*)(C16 + (size_t)r0 * N + col) = __floats2half2_rn(v0, v1);
                *(__half2*)(C16 + (size_t)(r0 + 8) * N + col) = __floats2half2_rn(v2, v3);
            }
        }
    }
}

// ---------------------------------------------------------------------------
// weight transpose+convert: W fp32 [K,N] -> T fp16 [N,K]
// ---------------------------------------------------------------------------
__global__ void wconv_kernel(const float* __restrict__ W, __half* __restrict__ T,
                             int K, int N)
{
    __shared__ float t[32][33];
    int n0 = blockIdx.x * 32, k0 = blockIdx.y * 32;
    int tx = threadIdx.x, ty = threadIdx.y;
    for (int r = ty; r < 32; r += 8)
        t[r][tx] = W[(size_t)(k0 + r) * N + n0 + tx];
    __syncthreads();
    for (int r = ty; r < 32; r += 8)
        T[(size_t)(n0 + r) * K + k0 + tx] = __float2half(t[tx][r]);
}

// fp32 -> fp16 convert (n multiple of 8)
__global__ void conv_kernel(const float* __restrict__ x, __half* __restrict__ y, size_t n)
{
    size_t i = ((size_t)blockIdx.x * blockDim.x + threadIdx.x) * 8;
    if (i >= n) return;
    float4 a = *(const float4*)(x + i);
    float4 b = *(const float4*)(x + i + 4);
    struct alignas(16) H8 { __half2 d[4]; } o;
    o.d[0] = __floats2half2_rn(a.x, a.y);
    o.d[1] = __floats2half2_rn(a.z, a.w);
    o.d[2] = __floats2half2_rn(b.x, b.y);
    o.d[3] = __floats2half2_rn(b.z, b.w);
    *(H8*)(y + i) = o;
}

// ---------------------------------------------------------------------------
// Linear-space minGRU scan: h <- h + z*(g - h), fp16 I/O, fp32 state
// ---------------------------------------------------------------------------
__global__ void scan_kernel(const __half* __restrict__ hg, __half* __restrict__ h)
{
    int idx = blockIdx.x * blockDim.x + threadIdx.x;
    int b = idx >> 10, c = idx & (HIsz - 1);
    const __half* base = hg + (size_t)b * Ssz * 2 * HIsz + c;
    __half* ho = h + (size_t)b * Ssz * HIsz + c;

    float hv = 0.f;
#pragma unroll 4
    for (int s = 0; s < Ssz; s++) {
        float hid  = __half2float(base[(size_t)s * 2 * HIsz]);
        float gate = __half2float(base[(size_t)s * 2 * HIsz + HIsz]);
        float z = __fdividef(1.f, 1.f + __expf(-gate));
        float g = (hid >= 0.f) ? (hid + 0.5f)
                               : __fdividef(1.f, 1.f + __expf(-hid));
        hv += z * (g - hv);
        ho[(size_t)s * HIsz] = __float2half(hv);
    }
}

// ---------------------------------------------------------------------------
// fp16 reverse-rotate: dst[b,s,:] = src[b, S-1-((s+S-len)%S), :]
// ---------------------------------------------------------------------------
__global__ void rev16_kernel(const __half* __restrict__ src, __half* __restrict__ dst,
                             const int* __restrict__ lens)
{
    int rIdx = blockIdx.x;
    int b = rIdx / Ssz, s = rIdx % Ssz;
    int len = lens[b];
    int t = s + Ssz - len; if (t >= Ssz) t -= Ssz;
    int sidx = Ssz - 1 - t;
    const float4* p = (const float4*)(src + ((size_t)b * Ssz + sidx) * Hsz);
    float4* q = (float4*)(dst + (size_t)rIdx * Hsz);
    q[threadIdx.x] = p[threadIdx.x];                 // 64 threads * 16B = 1KB row
}

__global__ void finalize_kernel(const float* __restrict__ xf, const float* __restrict__ xr,
                                const int* __restrict__ lens, float* __restrict__ out)
{
    int rIdx = blockIdx.x;
    int b = rIdx / Ssz, s = rIdx % Ssz;
    int len = lens[b];
    int t = s + Ssz - len; if (t >= Ssz) t -= Ssz;
    int sidx = Ssz - 1 - t;
    float4* o = (float4*)(out + (size_t)rIdx * 2 * Hsz);
    o[threadIdx.x]       = ((const float4*)(xf + (size_t)rIdx * Hsz))[threadIdx.x];
    o[128 + threadIdx.x] = ((const float4*)(xr + ((size_t)b * Ssz + sidx) * Hsz))[threadIdx.x];
}

__global__ void seq_kernel(const float* __restrict__ out, const int* __restrict__ lens,
                           float* __restrict__ seq)
{
    int b = blockIdx.x;
    int len = lens[b];
    const float* row = out + ((size_t)b * Ssz + (len - 1)) * 2 * Hsz;
    for (int j = threadIdx.x; j < 2 * Hsz; j += blockDim.x)
        seq[(size_t)b * 2 * Hsz + j] = row[j];
}

// ---------------------------------------------------------------------------
extern "C" void kernel_launch(void* const* d_in, const int* in_sizes, int n_in,
                              void* d_out, int out_size)
{
    const int*   x_source  = (const int*)  d_in[0];
    const int*   x_lengths = (const int*)  d_in[1];
    const float* emb       = (const float*)d_in[2];
    const float* W_er      = (const float*)d_in[3];
    const float* b_er      = (const float*)d_in[4];
    const float* Whg_f     = (const float*)d_in[5];
    const float* Wout_f    = (const float*)d_in[6];
    const float* Whg_r     = (const float*)d_in[7];
    const float* Wout_r    = (const float*)d_in[8];
    float* out = (float*)d_out;

    float *xf, *xr;
    __half *x16f, *x16r, *hg16, *h16, *emb16, *w16;
    cudaGetSymbolAddress((void**)&xf,    g_xf);
    cudaGetSymbolAddress((void**)&xr,    g_xr);
    cudaGetSymbolAddress((void**)&x16f,  g_x16f);
    cudaGetSymbolAddress((void**)&x16r,  g_x16r);
    cudaGetSymbolAddress((void**)&hg16,  g_hg16);
    cudaGetSymbolAddress((void**)&h16,   g_h16);
    cudaGetSymbolAddress((void**)&emb16, g_emb16);
    cudaGetSymbolAddress((void**)&w16,   g_w16);

    cudaFuncSetAttribute(gemm_kernel, cudaFuncAttributeMaxDynamicSharedMemorySize, GSM);

    // weight transpose+convert
    wconv_kernel<<<dim3(Hsz / 32, Esz / 32), dim3(32, 8)>>>(W_er, w16 + OFF_ER, Esz, Hsz);
    for (int l = 0; l < Lsz; l++) {
        wconv_kernel<<<dim3(2 * HIsz / 32, Hsz / 32), dim3(32, 8)>>>(
            Whg_f + (size_t)l * Hsz * 2 * HIsz, w16 + OFF_HGF + (size_t)l * 1048576, Hsz, 2 * HIsz);
        wconv_kernel<<<dim3(Hsz / 32, HIsz / 32), dim3(32, 8)>>>(
            Wout_f + (size_t)l * HIsz * Hsz, w16 + OFF_OUTF + (size_t)l * 524288, HIsz, Hsz);
        wconv_kernel<<<dim3(2 * HIsz / 32, Hsz / 32), dim3(32, 8)>>>(
            Whg_r + (size_t)l * Hsz * 2 * HIsz, w16 + OFF_HGR + (size_t)l * 1048576, Hsz, 2 * HIsz);
        wconv_kernel<<<dim3(Hsz / 32, HIsz / 32), dim3(32, 8)>>>(
            Wout_r + (size_t)l * HIsz * Hsz, w16 + OFF_OUTR + (size_t)l * 524288, HIsz, Hsz);
    }
    conv_kernel<<<(unsigned)(((size_t)Vsz * Esz) / 2048), 256>>>(emb, emb16, (size_t)Vsz * Esz);

    // embed GEMM -> x16f (+bias)
    gemm_kernel<<<dim3(Hsz / 128, Msz / 128), GT, GSM>>>(
        emb16, w16 + OFF_ER, nullptr, x16f, b_er, x_source, Hsz, Esz);

    rev16_kernel<<<Msz, 64>>>(x16f, x16r, x_lengths);

    for (int l = 0; l < Lsz; l++) {
        bool last = (l == Lsz - 1);
        // forward
        gemm_kernel<<<dim3(2 * HIsz / 128, Msz / 128), GT, GSM>>>(
            x16f, w16 + OFF_HGF + (size_t)l * 1048576, nullptr, hg16, nullptr, nullptr,
            2 * HIsz, Hsz);
        scan_kernel<<<(Bsz * HIsz) / 128, 128>>>(hg16, h16);
        gemm_kernel<<<dim3(Hsz / 128, Msz / 128), GT, GSM>>>(
            h16, w16 + OFF_OUTF + (size_t)l * 524288,
            last ? xf : nullptr, last ? nullptr : x16f, nullptr, nullptr, Hsz, HIsz);
        // reverse
        gemm_kernel<<<dim3(2 * HIsz / 128, Msz / 128), GT, GSM>>>(
            x16r, w16 + OFF_HGR + (size_t)l * 1048576, nullptr, hg16, nullptr, nullptr,
            2 * HIsz, Hsz);
        scan_kernel<<<(Bsz * HIsz) / 128, 128>>>(hg16, h16);
        gemm_kernel<<<dim3(Hsz / 128, Msz / 128), GT, GSM>>>(
            h16, w16 + OFF_OUTR + (size_t)l * 524288,
            last ? xr : nullptr, last ? nullptr : x16r, nullptr, nullptr, Hsz, HIsz);
    }

    finalize_kernel<<<Msz, 128>>>(xf, xr, x_lengths, out);
    long long need = (long long)Msz * 2 * Hsz + (long long)Bsz * 2 * Hsz;
    if ((long long)out_size >= need)
        seq_kernel<<<Bsz, 256>>>(out, x_lengths, out + (size_t)Msz * 2 * Hsz);
}

// round 5
// speedup vs baseline: 5.9589x; 1.1158x over previous
#include <cuda_runtime.h>
#include <cuda_fp16.h>
#include <math.h>
#include <stdint.h>

// Problem constants
#define Bsz  16
#define Ssz  2048
#define Esz  512
#define Hsz  512
#define HIsz 1024
#define Lsz  3
#define Msz  (Bsz * Ssz)
#define Vsz  32000

// ---------------------------------------------------------------------------
// Scratch (__device__ globals; allocation-free)
// ---------------------------------------------------------------------------
__device__ float  g_xf[(size_t)Msz * Hsz];
__device__ float  g_xr[(size_t)Msz * Hsz];
__device__ __half g_x16f[(size_t)Msz * Hsz];
__device__ __half g_x16r[(size_t)Msz * Hsz];
__device__ __half g_hg16f[(size_t)Msz * 2 * HIsz];
__device__ __half g_hg16r[(size_t)Msz * 2 * HIsz];
__device__ __half g_h16f[(size_t)Msz * HIsz];
__device__ __half g_h16r[(size_t)Msz * HIsz];
__device__ __half g_emb16[(size_t)Vsz * Esz];
#define NWELEM 9699328
__device__ __half g_w16[NWELEM];

#define OFF_ER    0
#define OFF_HGF   262144
#define OFF_OUTF  3407872
#define OFF_HGR   4980736
#define OFF_OUTR  8126464

// ---------------------------------------------------------------------------
// PTX helpers (baseline sm_103 ISA only)
// ---------------------------------------------------------------------------
__device__ __forceinline__ uint32_t s2u(const void* p) {
    uint32_t a;
    asm("{ .reg .u64 t; cvta.to.shared.u64 t, %1; cvt.u32.u64 %0, t; }" : "=r"(a) : "l"(p));
    return a;
}
__device__ __forceinline__ void cp16(uint32_t d, const void* s) {
    asm volatile("cp.async.cg.shared.global [%0], [%1], 16;" :: "r"(d), "l"(s));
}
__device__ __forceinline__ void cp_commit() { asm volatile("cp.async.commit_group;"); }
__device__ __forceinline__ void cp_wait2()  { asm volatile("cp.async.wait_group 2;"); }
__device__ __forceinline__ void ldm_x4(uint32_t addr, uint32_t& r0, uint32_t& r1,
                                       uint32_t& r2, uint32_t& r3) {
    asm volatile("ldmatrix.sync.aligned.m8n8.x4.shared.b16 {%0,%1,%2,%3}, [%4];"
                 : "=r"(r0), "=r"(r1), "=r"(r2), "=r"(r3) : "r"(addr));
}
__device__ __forceinline__ void mma_fp16(float& c0, float& c1, float& c2, float& c3,
                                         uint32_t a0, uint32_t a1, uint32_t a2, uint32_t a3,
                                         uint32_t b0, uint32_t b1) {
    asm volatile("mma.sync.aligned.m16n8k16.row.col.f32.f16.f16.f32 "
                 "{%0,%1,%2,%3}, {%4,%5,%6,%7}, {%8,%9}, {%0,%1,%2,%3};"
                 : "+f"(c0), "+f"(c1), "+f"(c2), "+f"(c3)
                 : "r"(a0), "r"(a1), "r"(a2), "r"(a3), "r"(b0), "r"(b1));
}

// ---------------------------------------------------------------------------
// fp16 GEMM, dual-problem batched over blockIdx.z.
// Tile 128x128, BK=32, 8 warps, 4-stage cp.async.
// ---------------------------------------------------------------------------
struct GArgs {
    const __half* A;        // [M,K] (row-gathered if rowidx)
    const __half* B;        // [N,K]
    float*        C32;      // optional fp32 out
    __half*       C16;      // optional fp16 out
    const float*  bias;     // optional
    const int*    rowidx;   // optional
};

#define GT 256
#define ROWB 80
#define TILE_B (128 * ROWB)
#define STAGE_B (2 * TILE_B)
#define GSM (4 * STAGE_B)

__global__ __launch_bounds__(GT, 2)
void gemm_kernel(GArgs ga0, GArgs ga1, int N, int K)
{
    extern __shared__ char smem[];
    const uint32_t sbase = s2u(smem);
    const GArgs ga = blockIdx.z ? ga1 : ga0;

    const int tid = threadIdx.x;
    const int wid = tid >> 5, lid = tid & 31;
    const int bm = blockIdx.y * 128, bn = blockIdx.x * 128;
    const int wm = (wid & 1) * 64;
    const int wn = (wid >> 1) * 32;

    const __half* gsrc[4];
    uint32_t soff[4];
#pragma unroll
    for (int j = 0; j < 4; j++) {
        int cidx = tid + j * GT;
        int tile = cidx >> 9;
        int idx  = cidx & 511;
        int row  = idx >> 2;
        int seg  = idx & 3;
        soff[j] = (uint32_t)(tile * TILE_B + row * ROWB + seg * 16);
        if (tile == 0) {
            long ra = ga.rowidx ? (long)ga.rowidx[bm + row] : (long)(bm + row);
            gsrc[j] = ga.A + ra * (long)K + seg * 8;
        } else {
            gsrc[j] = ga.B + (long)(bn + row) * K + seg * 8;
        }
    }

    uint32_t aoff[4];
#pragma unroll
    for (int mt = 0; mt < 4; mt++) {
        int r = wm + mt * 16 + (lid & 15);
        int c = (lid >> 4) * 8;
        aoff[mt] = (uint32_t)(r * ROWB + c * 2);
    }
    uint32_t boff[2];
#pragma unroll
    for (int np = 0; np < 2; np++) {
        int r = wn + np * 16 + (lid & 7) + ((lid >> 4) << 3);
        int c = ((lid >> 3) & 1) * 8;
        boff[np] = (uint32_t)(TILE_B + r * ROWB + c * 2);
    }

    float acc[4][4][4];
#pragma unroll
    for (int i = 0; i < 4; i++)
#pragma unroll
        for (int j = 0; j < 4; j++)
#pragma unroll
            for (int q = 0; q < 4; q++) acc[i][j][q] = 0.f;

    const int nst = K >> 5;

    auto load_stage = [&](int s) {
        uint32_t base = sbase + (uint32_t)(s & 3) * STAGE_B;
        int ko = s << 5;
#pragma unroll
        for (int j = 0; j < 4; j++) cp16(base + soff[j], gsrc[j] + ko);
    };

    load_stage(0); cp_commit();
    load_stage(1); cp_commit();
    load_stage(2); cp_commit();

    for (int s = 0; s < nst; s++) {
        cp_wait2();
        __syncthreads();
        if (s + 3 < nst) load_stage(s + 3);
        cp_commit();

        uint32_t base = sbase + (uint32_t)(s & 3) * STAGE_B;
#pragma unroll
        for (int k16 = 0; k16 < 2; k16++) {
            uint32_t koff = (uint32_t)(k16 * 32);
            uint32_t af[4][4];
#pragma unroll
            for (int mt = 0; mt < 4; mt++)
                ldm_x4(base + aoff[mt] + koff, af[mt][0], af[mt][1], af[mt][2], af[mt][3]);
            uint32_t bf[4][2];
#pragma unroll
            for (int np = 0; np < 2; np++) {
                uint32_t r0, r1, r2, r3;
                ldm_x4(base + boff[np] + koff, r0, r1, r2, r3);
                bf[np * 2][0] = r0;     bf[np * 2][1] = r1;
                bf[np * 2 + 1][0] = r2; bf[np * 2 + 1][1] = r3;
            }
#pragma unroll
            for (int mt = 0; mt < 4; mt++)
#pragma unroll
                for (int nt = 0; nt < 4; nt++)
                    mma_fp16(acc[mt][nt][0], acc[mt][nt][1], acc[mt][nt][2], acc[mt][nt][3],
                             af[mt][0], af[mt][1], af[mt][2], af[mt][3],
                             bf[nt][0], bf[nt][1]);
        }
    }

#pragma unroll
    for (int mt = 0; mt < 4; mt++) {
        int r0 = bm + wm + mt * 16 + (lid >> 2);
#pragma unroll
        for (int nt = 0; nt < 4; nt++) {
            int col = bn + wn + nt * 8 + (lid & 3) * 2;
            float v0 = acc[mt][nt][0], v1 = acc[mt][nt][1];
            float v2 = acc[mt][nt][2], v3 = acc[mt][nt][3];
            if (ga.bias) {
                float2 bb = *(const float2*)(ga.bias + col);
                v0 += bb.x; v1 += bb.y; v2 += bb.x; v3 += bb.y;
            }
            if (ga.C32) {
                *(float2*)(ga.C32 + (size_t)r0 * N + col) = make_float2(v0, v1);
                *(float2*)(ga.C32 + (size_t)(r0 + 8) * N + col) = make_float2(v2, v3);
            }
            if (ga.C16) {
                *(__half2*)(ga.C16 + (size_t)r0 * N + col) = __floats2half2_rn(v0, v1);
                *(__half2*)(ga.C16 + (size_t)(r0 + 8) * N + col) = __floats2half2_rn(v2, v3);
            }
        }
    }
}

// ---------------------------------------------------------------------------
// weight transpose+convert, batched over 6 (dir,layer) with blockIdx.z
// ---------------------------------------------------------------------------
__global__ void wconv_batch_kernel(const float* __restrict__ Wf, const float* __restrict__ Wr,
                                   __half* __restrict__ Tf, __half* __restrict__ Tr,
                                   int K, int N)
{
    __shared__ float t[32][33];
    int z = blockIdx.z;
    int l = (z >= 3) ? z - 3 : z;
    const float* W = ((z >= 3) ? Wr : Wf) + (size_t)l * K * N;
    __half*      T = ((z >= 3) ? Tr : Tf) + (size_t)l * K * N;
    int n0 = blockIdx.x * 32, k0 = blockIdx.y * 32;
    int tx = threadIdx.x, ty = threadIdx.y;
    for (int r = ty; r < 32; r += 8)
        t[r][tx] = W[(size_t)(k0 + r) * N + n0 + tx];
    __syncthreads();
    for (int r = ty; r < 32; r += 8)
        T[(size_t)(n0 + r) * K + k0 + tx] = __float2half(t[tx][r]);
}

__global__ void wconv_kernel(const float* __restrict__ W, __half* __restrict__ T,
                             int K, int N)
{
    __shared__ float t[32][33];
    int n0 = blockIdx.x * 32, k0 = blockIdx.y * 32;
    int tx = threadIdx.x, ty = threadIdx.y;
    for (int r = ty; r < 32; r += 8)
        t[r][tx] = W[(size_t)(k0 + r) * N + n0 + tx];
    __syncthreads();
    for (int r = ty; r < 32; r += 8)
        T[(size_t)(n0 + r) * K + k0 + tx] = __float2half(t[tx][r]);
}

__global__ void conv_kernel(const float* __restrict__ x, __half* __restrict__ y, size_t n)
{
    size_t i = ((size_t)blockIdx.x * blockDim.x + threadIdx.x) * 8;
    if (i >= n) return;
    float4 a = *(const float4*)(x + i);
    float4 b = *(const float4*)(x + i + 4);
    struct alignas(16) H8 { __half2 d[4]; } o;
    o.d[0] = __floats2half2_rn(a.x, a.y);
    o.d[1] = __floats2half2_rn(a.z, a.w);
    o.d[2] = __floats2half2_rn(b.x, b.y);
    o.d[3] = __floats2half2_rn(b.z, b.w);
    *(H8*)(y + i) = o;
}

// ---------------------------------------------------------------------------
// Linear minGRU scan, both directions (blockIdx.z), 2 channels/thread,
// 8-step register prefetch (double buffer).  grid (64,1,2), block 128.
// ---------------------------------------------------------------------------
#define SCU 8
__global__ void scan_kernel(const __half2* __restrict__ hgF, const __half2* __restrict__ hgR,
                            __half2* __restrict__ hF, __half2* __restrict__ hR)
{
    int idx = blockIdx.x * blockDim.x + threadIdx.x;   // 0..8191
    int b = idx >> 9, c2 = idx & 511;
    const __half2* p = (blockIdx.z ? hgR : hgF) + (size_t)b * Ssz * HIsz + c2; // row = HIsz half2
    __half2* ho = (blockIdx.z ? hR : hF) + (size_t)b * Ssz * (HIsz / 2) + c2;  // row = 512 half2

    float h0 = 0.f, h1 = 0.f;
    __half2 bH[SCU], bG[SCU];
#pragma unroll
    for (int u = 0; u < SCU; u++) {
        bH[u] = p[(size_t)u * HIsz];
        bG[u] = p[(size_t)u * HIsz + 512];
    }

    const float L2E = 1.44269504f;
    for (int blk = 0; blk < Ssz / SCU; blk++) {
        __half2 nH[SCU], nG[SCU];
        const __half2* nxt = p + (size_t)SCU * HIsz;
        bool more = (blk + 1 < Ssz / SCU);
#pragma unroll
        for (int u = 0; u < SCU; u++) {
            if (more) {
                nH[u] = nxt[(size_t)u * HIsz];
                nG[u] = nxt[(size_t)u * HIsz + 512];
            }
        }
#pragma unroll
        for (int u = 0; u < SCU; u++) {
            float2 hid = __half22float2(bH[u]);
            float2 gt  = __half22float2(bG[u]);
            float z0 = __frcp_rn(1.f + exp2f(-gt.x * L2E));
            float z1 = __frcp_rn(1.f + exp2f(-gt.y * L2E));
            float g0 = (hid.x >= 0.f) ? (hid.x + 0.5f) : __frcp_rn(1.f + exp2f(-hid.x * L2E));
            float g1 = (hid.y >= 0.f) ? (hid.y + 0.5f) : __frcp_rn(1.f + exp2f(-hid.y * L2E));
            h0 += z0 * (g0 - h0);
            h1 += z1 * (g1 - h1);
            ho[(size_t)(blk * SCU + u) * 512] = __floats2half2_rn(h0, h1);
        }
#pragma unroll
        for (int u = 0; u < SCU; u++) { bH[u] = nH[u]; bG[u] = nG[u]; }
        p = nxt;
    }
}

// ---------------------------------------------------------------------------
// shuffles / gathers
// ---------------------------------------------------------------------------
__global__ void rev16_kernel(const __half* __restrict__ src, __half* __restrict__ dst,
                             const int* __restrict__ lens)
{
    int rIdx = blockIdx.x;
    int b = rIdx / Ssz, s = rIdx % Ssz;
    int len = lens[b];
    int t = s + Ssz - len; if (t >= Ssz) t -= Ssz;
    int sidx = Ssz - 1 - t;
    const float4* p = (const float4*)(src + ((size_t)b * Ssz + sidx) * Hsz);
    float4* q = (float4*)(dst + (size_t)rIdx * Hsz);
    q[threadIdx.x] = p[threadIdx.x];
}

__global__ void finalize_kernel(const float* __restrict__ xf, const float* __restrict__ xr,
                                const int* __restrict__ lens, float* __restrict__ out)
{
    int rIdx = blockIdx.x;
    int b = rIdx / Ssz, s = rIdx % Ssz;
    int len = lens[b];
    int t = s + Ssz - len; if (t >= Ssz) t -= Ssz;
    int sidx = Ssz - 1 - t;
    float4* o = (float4*)(out + (size_t)rIdx * 2 * Hsz);
    o[threadIdx.x]       = ((const float4*)(xf + (size_t)rIdx * Hsz))[threadIdx.x];
    o[128 + threadIdx.x] = ((const float4*)(xr + ((size_t)b * Ssz + sidx) * Hsz))[threadIdx.x];
}

__global__ void seq_kernel(const float* __restrict__ out, const int* __restrict__ lens,
                           float* __restrict__ seq)
{
    int b = blockIdx.x;
    int len = lens[b];
    const float* row = out + ((size_t)b * Ssz + (len - 1)) * 2 * Hsz;
    for (int j = threadIdx.x; j < 2 * Hsz; j += blockDim.x)
        seq[(size_t)b * 2 * Hsz + j] = row[j];
}

// ---------------------------------------------------------------------------
extern "C" void kernel_launch(void* const* d_in, const int* in_sizes, int n_in,
                              void* d_out, int out_size)
{
    const int*   x_source  = (const int*)  d_in[0];
    const int*   x_lengths = (const int*)  d_in[1];
    const float* emb       = (const float*)d_in[2];
    const float* W_er      = (const float*)d_in[3];
    const float* b_er      = (const float*)d_in[4];
    const float* Whg_f     = (const float*)d_in[5];
    const float* Wout_f    = (const float*)d_in[6];
    const float* Whg_r     = (const float*)d_in[7];
    const float* Wout_r    = (const float*)d_in[8];
    float* out = (float*)d_out;

    float *xf, *xr;
    __half *x16f, *x16r, *hg16f, *hg16r, *h16f, *h16r, *emb16, *w16;
    cudaGetSymbolAddress((void**)&xf,    g_xf);
    cudaGetSymbolAddress((void**)&xr,    g_xr);
    cudaGetSymbolAddress((void**)&x16f,  g_x16f);
    cudaGetSymbolAddress((void**)&x16r,  g_x16r);
    cudaGetSymbolAddress((void**)&hg16f, g_hg16f);
    cudaGetSymbolAddress((void**)&hg16r, g_hg16r);
    cudaGetSymbolAddress((void**)&h16f,  g_h16f);
    cudaGetSymbolAddress((void**)&h16r,  g_h16r);
    cudaGetSymbolAddress((void**)&emb16, g_emb16);
    cudaGetSymbolAddress((void**)&w16,   g_w16);

    cudaFuncSetAttribute(gemm_kernel, cudaFuncAttributeMaxDynamicSharedMemorySize, GSM);

    // weight converts (batched)
    wconv_batch_kernel<<<dim3(2 * HIsz / 32, Hsz / 32, 6), dim3(32, 8)>>>(
        Whg_f, Whg_r, w16 + OFF_HGF, w16 + OFF_HGR, Hsz, 2 * HIsz);
    wconv_batch_kernel<<<dim3(Hsz / 32, HIsz / 32, 6), dim3(32, 8)>>>(
        Wout_f, Wout_r, w16 + OFF_OUTF, w16 + OFF_OUTR, HIsz, Hsz);
    wconv_kernel<<<dim3(Hsz / 32, Esz / 32), dim3(32, 8)>>>(W_er, w16 + OFF_ER, Esz, Hsz);
    conv_kernel<<<(unsigned)(((size_t)Vsz * Esz) / 2048), 256>>>(emb, emb16, (size_t)Vsz * Esz);

    // embed GEMM -> x16f
    {
        GArgs a0 = { emb16, w16 + OFF_ER, nullptr, x16f, b_er, x_source };
        gemm_kernel<<<dim3(Hsz / 128, Msz / 128, 1), GT, GSM>>>(a0, a0, Hsz, Esz);
    }
    rev16_kernel<<<Msz, 64>>>(x16f, x16r, x_lengths);

    for (int l = 0; l < Lsz; l++) {
        bool last = (l == Lsz - 1);
        // gate GEMMs (both dirs)
        {
            GArgs a0 = { x16f, w16 + OFF_HGF + (size_t)l * 1048576, nullptr, hg16f, nullptr, nullptr };
            GArgs a1 = { x16r, w16 + OFF_HGR + (size_t)l * 1048576, nullptr, hg16r, nullptr, nullptr };
            gemm_kernel<<<dim3(2 * HIsz / 128, Msz / 128, 2), GT, GSM>>>(a0, a1, 2 * HIsz, Hsz);
        }
        // scans (both dirs)
        scan_kernel<<<dim3(64, 1, 2), 128>>>((const __half2*)hg16f, (const __half2*)hg16r,
                                             (__half2*)h16f, (__half2*)h16r);
        // output GEMMs (both dirs)
        {
            GArgs a0 = { h16f, w16 + OFF_OUTF + (size_t)l * 524288,
                         last ? xf : nullptr, last ? nullptr : x16f, nullptr, nullptr };
            GArgs a1 = { h16r, w16 + OFF_OUTR + (size_t)l * 524288,
                         last ? xr : nullptr, last ? nullptr : x16r, nullptr, nullptr };
            gemm_kernel<<<dim3(Hsz / 128, Msz / 128, 2), GT, GSM>>>(a0, a1, Hsz, HIsz);
        }
    }

    finalize_kernel<<<Msz, 128>>>(xf, xr, x_lengths, out);
    long long need = (long long)Msz * 2 * Hsz + (long long)Bsz * 2 * Hsz;
    if ((long long)out_size >= need)
        seq_kernel<<<Bsz, 256>>>(out, x_lengths, out + (size_t)Msz * 2 * Hsz);
}

// round 6
// speedup vs baseline: 10.0505x; 1.6867x over previous
#include <cuda_runtime.h>
#include <cuda_fp16.h>
#include <math.h>
#include <stdint.h>

// Problem constants
#define Bsz  16
#define Ssz  2048
#define Esz  512
#define Hsz  512
#define HIsz 1024
#define Lsz  3
#define Msz  (Bsz * Ssz)
#define Vsz  32000

// ---------------------------------------------------------------------------
// Scratch (__device__ globals; allocation-free)
// ---------------------------------------------------------------------------
__device__ __half g_x16f[(size_t)Msz * Hsz];
__device__ __half g_x16r[(size_t)Msz * Hsz];
__device__ __half g_hg16f[(size_t)Msz * 2 * HIsz];
__device__ __half g_hg16r[(size_t)Msz * 2 * HIsz];
__device__ __half g_h16f[(size_t)Msz * HIsz];
__device__ __half g_h16r[(size_t)Msz * HIsz];
__device__ __half g_emb16[(size_t)Vsz * Esz];
#define NWELEM 9699328
__device__ __half g_w16[NWELEM];

#define OFF_ER    0
#define OFF_HGF   262144
#define OFF_OUTF  3407872
#define OFF_HGR   4980736
#define OFF_OUTR  8126464

// ---------------------------------------------------------------------------
// PTX helpers (baseline sm_103 ISA only)
// ---------------------------------------------------------------------------
__device__ __forceinline__ uint32_t s2u(const void* p) {
    uint32_t a;
    asm("{ .reg .u64 t; cvta.to.shared.u64 t, %1; cvt.u32.u64 %0, t; }" : "=r"(a) : "l"(p));
    return a;
}
__device__ __forceinline__ void cp16(uint32_t d, const void* s) {
    asm volatile("cp.async.cg.shared.global [%0], [%1], 16;" :: "r"(d), "l"(s));
}
__device__ __forceinline__ void cp_commit() { asm volatile("cp.async.commit_group;"); }
__device__ __forceinline__ void cp_wait2()  { asm volatile("cp.async.wait_group 2;"); }
__device__ __forceinline__ void ldm_x4(uint32_t addr, uint32_t& r0, uint32_t& r1,
                                       uint32_t& r2, uint32_t& r3) {
    asm volatile("ldmatrix.sync.aligned.m8n8.x4.shared.b16 {%0,%1,%2,%3}, [%4];"
                 : "=r"(r0), "=r"(r1), "=r"(r2), "=r"(r3) : "r"(addr));
}
__device__ __forceinline__ void mma_fp16(float& c0, float& c1, float& c2, float& c3,
                                         uint32_t a0, uint32_t a1, uint32_t a2, uint32_t a3,
                                         uint32_t b0, uint32_t b1) {
    asm volatile("mma.sync.aligned.m16n8k16.row.col.f32.f16.f16.f32 "
                 "{%0,%1,%2,%3}, {%4,%5,%6,%7}, {%8,%9}, {%0,%1,%2,%3};"
                 : "+f"(c0), "+f"(c1), "+f"(c2), "+f"(c3)
                 : "r"(a0), "r"(a1), "r"(a2), "r"(a3), "r"(b0), "r"(b1));
}

// rev row mapping: r -> same b, flipped+rotated s
__device__ __forceinline__ int revrow(int r, int len) {
    int s = r & (Ssz - 1);
    int t = s + Ssz - len; if (t >= Ssz) t -= Ssz;
    return (r & ~(Ssz - 1)) + (Ssz - 1 - t);
}

// ---------------------------------------------------------------------------
// fp16 GEMM, dual-problem batched over blockIdx.z.
// Tile 128x128, BK=32, 8 warps, 4-stage cp.async.
// Epilogue can write: C32 (fp32, optional rev row-map, stride/coloff),
// C16 (fp16 plain), C16b (fp16 rev row-mapped copy).
// ---------------------------------------------------------------------------
struct GArgs {
    const __half* A;
    const __half* B;
    float*        C32;
    __half*       C16;
    __half*       C16b;
    const float*  bias;
    const int*    rowidx;
    const int*    lens;
    int cstride;
    int coloff;
    int c32rev;
};

#define GT 256
#define ROWB 80
#define TILE_B (128 * ROWB)
#define STAGE_B (2 * TILE_B)
#define GSM (4 * STAGE_B)

__global__ __launch_bounds__(GT, 2)
void gemm_kernel(GArgs ga0, GArgs ga1, int N, int K)
{
    extern __shared__ char smem[];
    const uint32_t sbase = s2u(smem);
    const GArgs ga = blockIdx.z ? ga1 : ga0;

    const int tid = threadIdx.x;
    const int wid = tid >> 5, lid = tid & 31;
    const int bm = blockIdx.y * 128, bn = blockIdx.x * 128;
    const int wm = (wid & 1) * 64;
    const int wn = (wid >> 1) * 32;

    const __half* gsrc[4];
    uint32_t soff[4];
#pragma unroll
    for (int j = 0; j < 4; j++) {
        int cidx = tid + j * GT;
        int tile = cidx >> 9;
        int idx  = cidx & 511;
        int row  = idx >> 2;
        int seg  = idx & 3;
        soff[j] = (uint32_t)(tile * TILE_B + row * ROWB + seg * 16);
        if (tile == 0) {
            long ra = ga.rowidx ? (long)ga.rowidx[bm + row] : (long)(bm + row);
            gsrc[j] = ga.A + ra * (long)K + seg * 8;
        } else {
            gsrc[j] = ga.B + (long)(bn + row) * K + seg * 8;
        }
    }

    uint32_t aoff[4];
#pragma unroll
    for (int mt = 0; mt < 4; mt++) {
        int r = wm + mt * 16 + (lid & 15);
        int c = (lid >> 4) * 8;
        aoff[mt] = (uint32_t)(r * ROWB + c * 2);
    }
    uint32_t boff[2];
#pragma unroll
    for (int np = 0; np < 2; np++) {
        int r = wn + np * 16 + (lid & 7) + ((lid >> 4) << 3);
        int c = ((lid >> 3) & 1) * 8;
        boff[np] = (uint32_t)(TILE_B + r * ROWB + c * 2);
    }

    float acc[4][4][4];
#pragma unroll
    for (int i = 0; i < 4; i++)
#pragma unroll
        for (int j = 0; j < 4; j++)
#pragma unroll
            for (int q = 0; q < 4; q++) acc[i][j][q] = 0.f;

    const int nst = K >> 5;

    auto load_stage = [&](int s) {
        uint32_t base = sbase + (uint32_t)(s & 3) * STAGE_B;
        int ko = s << 5;
#pragma unroll
        for (int j = 0; j < 4; j++) cp16(base + soff[j], gsrc[j] + ko);
    };

    load_stage(0); cp_commit();
    load_stage(1); cp_commit();
    load_stage(2); cp_commit();

    for (int s = 0; s < nst; s++) {
        cp_wait2();
        __syncthreads();
        if (s + 3 < nst) load_stage(s + 3);
        cp_commit();

        uint32_t base = sbase + (uint32_t)(s & 3) * STAGE_B;
#pragma unroll
        for (int k16 = 0; k16 < 2; k16++) {
            uint32_t koff = (uint32_t)(k16 * 32);
            uint32_t af[4][4];
#pragma unroll
            for (int mt = 0; mt < 4; mt++)
                ldm_x4(base + aoff[mt] + koff, af[mt][0], af[mt][1], af[mt][2], af[mt][3]);
            uint32_t bf[4][2];
#pragma unroll
            for (int np = 0; np < 2; np++) {
                uint32_t r0, r1, r2, r3;
                ldm_x4(base + boff[np] + koff, r0, r1, r2, r3);
                bf[np * 2][0] = r0;     bf[np * 2][1] = r1;
                bf[np * 2 + 1][0] = r2; bf[np * 2 + 1][1] = r3;
            }
#pragma unroll
            for (int mt = 0; mt < 4; mt++)
#pragma unroll
                for (int nt = 0; nt < 4; nt++)
                    mma_fp16(acc[mt][nt][0], acc[mt][nt][1], acc[mt][nt][2], acc[mt][nt][3],
                             af[mt][0], af[mt][1], af[mt][2], af[mt][3],
                             bf[nt][0], bf[nt][1]);
        }
    }

    // ---- epilogue ----
    int len = ga.lens ? ga.lens[bm >> 11] : 0;    // 128-row tile stays in one b
#pragma unroll
    for (int mt = 0; mt < 4; mt++) {
        int rA = bm + wm + mt * 16 + (lid >> 2);
        int rB = rA + 8;
        int rAm = ga.lens ? revrow(rA, len) : 0;
        int rBm = ga.lens ? revrow(rB, len) : 0;
#pragma unroll
        for (int nt = 0; nt < 4; nt++) {
            int col = bn + wn + nt * 8 + (lid & 3) * 2;
            float v0 = acc[mt][nt][0], v1 = acc[mt][nt][1];
            float v2 = acc[mt][nt][2], v3 = acc[mt][nt][3];
            if (ga.bias) {
                float2 bb = *(const float2*)(ga.bias + col);
                v0 += bb.x; v1 += bb.y; v2 += bb.x; v3 += bb.y;
            }
            if (ga.C32) {
                int wA = ga.c32rev ? rAm : rA;
                int wB = ga.c32rev ? rBm : rB;
                *(float2*)(ga.C32 + (size_t)wA * ga.cstride + ga.coloff + col) = make_float2(v0, v1);
                *(float2*)(ga.C32 + (size_t)wB * ga.cstride + ga.coloff + col) = make_float2(v2, v3);
            }
            if (ga.C16) {
                *(__half2*)(ga.C16 + (size_t)rA * ga.cstride + col) = __floats2half2_rn(v0, v1);
                *(__half2*)(ga.C16 + (size_t)rB * ga.cstride + col) = __floats2half2_rn(v2, v3);
            }
            if (ga.C16b) {
                *(__half2*)(ga.C16b + (size_t)rAm * ga.cstride + col) = __floats2half2_rn(v0, v1);
                *(__half2*)(ga.C16b + (size_t)rBm * ga.cstride + col) = __floats2half2_rn(v2, v3);
            }
        }
    }
}

// ---------------------------------------------------------------------------
// weight transpose+convert
// ---------------------------------------------------------------------------
__global__ void wconv_batch_kernel(const float* __restrict__ Wf, const float* __restrict__ Wr,
                                   __half* __restrict__ Tf, __half* __restrict__ Tr,
                                   int K, int N)
{
    __shared__ float t[32][33];
    int z = blockIdx.z;
    int l = (z >= 3) ? z - 3 : z;
    const float* W = ((z >= 3) ? Wr : Wf) + (size_t)l * K * N;
    __half*      T = ((z >= 3) ? Tr : Tf) + (size_t)l * K * N;
    int n0 = blockIdx.x * 32, k0 = blockIdx.y * 32;
    int tx = threadIdx.x, ty = threadIdx.y;
    for (int r = ty; r < 32; r += 8)
        t[r][tx] = W[(size_t)(k0 + r) * N + n0 + tx];
    __syncthreads();
    for (int r = ty; r < 32; r += 8)
        T[(size_t)(n0 + r) * K + k0 + tx] = __float2half(t[tx][r]);
}

__global__ void wconv_kernel(const float* __restrict__ W, __half* __restrict__ T,
                             int K, int N)
{
    __shared__ float t[32][33];
    int n0 = blockIdx.x * 32, k0 = blockIdx.y * 32;
    int tx = threadIdx.x, ty = threadIdx.y;
    for (int r = ty; r < 32; r += 8)
        t[r][tx] = W[(size_t)(k0 + r) * N + n0 + tx];
    __syncthreads();
    for (int r = ty; r < 32; r += 8)
        T[(size_t)(n0 + r) * K + k0 + tx] = __float2half(t[tx][r]);
}

__global__ void conv_kernel(const float* __restrict__ x, __half* __restrict__ y, size_t n)
{
    size_t i = ((size_t)blockIdx.x * blockDim.x + threadIdx.x) * 8;
    if (i >= n) return;
    float4 a = *(const float4*)(x + i);
    float4 b = *(const float4*)(x + i + 4);
    struct alignas(16) H8 { __half2 d[4]; } o;
    o.d[0] = __floats2half2_rn(a.x, a.y);
    o.d[1] = __floats2half2_rn(a.z, a.w);
    o.d[2] = __floats2half2_rn(b.x, b.y);
    o.d[3] = __floats2half2_rn(b.z, b.w);
    *(H8*)(y + i) = o;
}

// ---------------------------------------------------------------------------
// Linear minGRU scan — cp.async smem-pipelined streaming version.
// 1 channel/thread. grid (128, 2): x = (b, channel-block), y = direction.
// Stage = 16 steps x 128 channels x (H+G) = 8 KB; 4 stages.
// ---------------------------------------------------------------------------
#define SCT 16
#define SSTAGE_B 8192

__global__ __launch_bounds__(128, 2)
void scan_kernel(const __half* __restrict__ hgF, const __half* __restrict__ hgR,
                 __half* __restrict__ hF, __half* __restrict__ hR)
{
    __shared__ char smem[4 * SSTAGE_B];
    const uint32_t sb = s2u(smem);
    const int tid = threadIdx.x;
    const int b = blockIdx.x >> 3;
    const int cblk = (blockIdx.x & 7) << 7;
    const int c = cblk + tid;
    const int dir = blockIdx.y;

    const __half* hgp = (dir ? hgR : hgF) + (size_t)b * Ssz * 2 * HIsz;
    __half* hp = (dir ? hR : hF) + (size_t)b * Ssz * HIsz + c;

    // load slots: 4 cp16 per thread per stage
    const __half* gsl[4];
    uint32_t ssl[4];
#pragma unroll
    for (int j = 0; j < 4; j++) {
        int lin = tid + 128 * j;            // 0..511
        int u   = lin >> 5;                 // step 0..15
        int prt = lin & 31;
        int isg = prt >> 4;                 // 0: hidden, 1: gate
        int seg = prt & 15;                 // 16B segment of 256B row
        gsl[j] = hgp + (size_t)u * 2 * HIsz + (size_t)isg * HIsz + cblk + seg * 8;
        ssl[j] = (uint32_t)(u * 512 + isg * 256 + seg * 16);
    }

    auto load_stage = [&](int st) {
        uint32_t base = sb + (uint32_t)(st & 3) * SSTAGE_B;
        size_t go = (size_t)st * SCT * 2 * HIsz;
#pragma unroll
        for (int j = 0; j < 4; j++) cp16(base + ssl[j], gsl[j] + go);
        cp_commit();
    };

    load_stage(0);
    load_stage(1);
    load_stage(2);

    const int NST = Ssz / SCT;              // 128
    float h = 0.f;
    for (int st = 0; st < NST; st++) {
        cp_wait2();
        __syncthreads();
        if (st + 3 < NST) load_stage(st + 3);

        const __half* base = (const __half*)(smem + (size_t)(st & 3) * SSTAGE_B);
#pragma unroll
        for (int u = 0; u < SCT; u++) {
            float hid  = __half2float(base[u * 256 + tid]);
            float gate = __half2float(base[u * 256 + 128 + tid]);
            float z = __fdividef(1.f, 1.f + __expf(-gate));
            float g = (hid >= 0.f) ? (hid + 0.5f)
                                   : __fdividef(1.f, 1.f + __expf(-hid));
            h += z * (g - h);
            hp[(size_t)(st * SCT + u) * HIsz] = __float2half(h);
        }
    }
}

// ---------------------------------------------------------------------------
// seq_h[b,:] = out[b, len[b]-1, :]
// ---------------------------------------------------------------------------
__global__ void seq_kernel(const float* __restrict__ out, const int* __restrict__ lens,
                           float* __restrict__ seq)
{
    int b = blockIdx.x;
    int len = lens[b];
    const float* row = out + ((size_t)b * Ssz + (len - 1)) * 2 * Hsz;
    for (int j = threadIdx.x; j < 2 * Hsz; j += blockDim.x)
        seq[(size_t)b * 2 * Hsz + j] = row[j];
}

// ---------------------------------------------------------------------------
extern "C" void kernel_launch(void* const* d_in, const int* in_sizes, int n_in,
                              void* d_out, int out_size)
{
    const int*   x_source  = (const int*)  d_in[0];
    const int*   x_lengths = (const int*)  d_in[1];
    const float* emb       = (const float*)d_in[2];
    const float* W_er      = (const float*)d_in[3];
    const float* b_er      = (const float*)d_in[4];
    const float* Whg_f     = (const float*)d_in[5];
    const float* Wout_f    = (const float*)d_in[6];
    const float* Whg_r     = (const float*)d_in[7];
    const float* Wout_r    = (const float*)d_in[8];
    float* out = (float*)d_out;

    __half *x16f, *x16r, *hg16f, *hg16r, *h16f, *h16r, *emb16, *w16;
    cudaGetSymbolAddress((void**)&x16f,  g_x16f);
    cudaGetSymbolAddress((void**)&x16r,  g_x16r);
    cudaGetSymbolAddress((void**)&hg16f, g_hg16f);
    cudaGetSymbolAddress((void**)&hg16r, g_hg16r);
    cudaGetSymbolAddress((void**)&h16f,  g_h16f);
    cudaGetSymbolAddress((void**)&h16r,  g_h16r);
    cudaGetSymbolAddress((void**)&emb16, g_emb16);
    cudaGetSymbolAddress((void**)&w16,   g_w16);

    cudaFuncSetAttribute(gemm_kernel, cudaFuncAttributeMaxDynamicSharedMemorySize, GSM);

    // weight converts
    wconv_batch_kernel<<<dim3(2 * HIsz / 32, Hsz / 32, 6), dim3(32, 8)>>>(
        Whg_f, Whg_r, w16 + OFF_HGF, w16 + OFF_HGR, Hsz, 2 * HIsz);
    wconv_batch_kernel<<<dim3(Hsz / 32, HIsz / 32, 6), dim3(32, 8)>>>(
        Wout_f, Wout_r, w16 + OFF_OUTF, w16 + OFF_OUTR, HIsz, Hsz);
    wconv_kernel<<<dim3(Hsz / 32, Esz / 32), dim3(32, 8)>>>(W_er, w16 + OFF_ER, Esz, Hsz);
    conv_kernel<<<(unsigned)(((size_t)Vsz * Esz) / 2048), 256>>>(emb, emb16, (size_t)Vsz * Esz);

    // embed GEMM -> x16f and rev-rotated x16r (fused)
    {
        GArgs a0 = { emb16, w16 + OFF_ER, nullptr, x16f, x16r, b_er, x_source, x_lengths,
                     Hsz, 0, 0 };
        gemm_kernel<<<dim3(Hsz / 128, Msz / 128, 1), GT, GSM>>>(a0, a0, Hsz, Esz);
    }

    for (int l = 0; l < Lsz; l++) {
        bool last = (l == Lsz - 1);
        // gate GEMMs (both dirs)
        {
            GArgs a0 = { x16f, w16 + OFF_HGF + (size_t)l * 1048576, nullptr, hg16f, nullptr,
                         nullptr, nullptr, nullptr, 2 * HIsz, 0, 0 };
            GArgs a1 = { x16r, w16 + OFF_HGR + (size_t)l * 1048576, nullptr, hg16r, nullptr,
                         nullptr, nullptr, nullptr, 2 * HIsz, 0, 0 };
            gemm_kernel<<<dim3(2 * HIsz / 128, Msz / 128, 2), GT, GSM>>>(a0, a1, 2 * HIsz, Hsz);
        }
        // scans (both dirs)
        scan_kernel<<<dim3(128, 2), 128>>>(hg16f, hg16r, h16f, h16r);
        // output GEMMs (both dirs)
        if (!last) {
            GArgs a0 = { h16f, w16 + OFF_OUTF + (size_t)l * 524288, nullptr, x16f, nullptr,
                         nullptr, nullptr, nullptr, Hsz, 0, 0 };
            GArgs a1 = { h16r, w16 + OFF_OUTR + (size_t)l * 524288, nullptr, x16r, nullptr,
                         nullptr, nullptr, nullptr, Hsz, 0, 0 };
            gemm_kernel<<<dim3(Hsz / 128, Msz / 128, 2), GT, GSM>>>(a0, a1, Hsz, HIsz);
        } else {
            // write fp32 directly into out: fwd at cols [0,H), rev (row-remapped) at [H,2H)
            GArgs a0 = { h16f, w16 + OFF_OUTF + (size_t)l * 524288, out, nullptr, nullptr,
                         nullptr, nullptr, x_lengths, 2 * Hsz, 0, 0 };
            GArgs a1 = { h16r, w16 + OFF_OUTR + (size_t)l * 524288, out, nullptr, nullptr,
                         nullptr, nullptr, x_lengths, 2 * Hsz, Hsz, 1 };
            gemm_kernel<<<dim3(Hsz / 128, Msz / 128, 2), GT, GSM>>>(a0, a1, Hsz, HIsz);
        }
    }

    long long need = (long long)Msz * 2 * Hsz + (long long)Bsz * 2 * Hsz;
    if ((long long)out_size >= need)
        seq_kernel<<<Bsz, 256>>>(out, x_lengths, out + (size_t)Msz * 2 * Hsz);
}